// round 2
// baseline (speedup 1.0000x reference)
#include <cuda_runtime.h>

#define Hh 160
#define Ww 160
#define Bn 4
#define HW (Hh*Ww)

// ---------------- scratch (device globals; no allocation allowed) ----------------
__device__ float g_h1[(size_t)Bn*128*HW];     // conv1 out
__device__ float g_h2[(size_t)Bn*128*HW];     // conv2 out
__device__ float g_off[(size_t)Bn*18*HW];     // offset conv out
__device__ float g_hrT[(size_t)Bn*HW*64];     // hr in NHWC
__device__ float g_samp[(size_t)Bn*576*HW];   // bilinear samples, [b][c*9+k][h][w]
__device__ float g_w1T[1152*128];
__device__ float g_w2T[1152*128];
__device__ float g_woT[1152*32];              // padded 18 -> 32
__device__ float g_wdT[576*64];

// ---------------- packed f32x2 helpers ----------------
__device__ __forceinline__ unsigned long long ffma2(unsigned long long a,
                                                    unsigned long long b,
                                                    unsigned long long c)
{
    unsigned long long d;
    asm("fma.rn.f32x2 %0, %1, %2, %3;" : "=l"(d) : "l"(a), "l"(b), "l"(c));
    return d;
}
__device__ __forceinline__ unsigned long long pack2(float lo, float hi)
{
    unsigned long long d;
    asm("mov.b64 %0, {%1, %2};" : "=l"(d) : "f"(lo), "f"(hi));
    return d;
}
__device__ __forceinline__ float2 unpack2(unsigned long long v)
{
    float lo, hi;
    asm("mov.b64 {%0, %1}, %2;" : "=f"(lo), "=f"(hi) : "l"(v));
    return make_float2(lo, hi);
}

// ---------------- weight reformat: [O][CINK] -> [CINK][O_pad] (zero padded) ----------------
__global__ void transpose_w(const float* __restrict__ w, float* __restrict__ wT,
                            int COUT, int COUT_PAD, int CINK)
{
    int i = blockIdx.x*blockDim.x + threadIdx.x;
    if (i >= CINK*COUT_PAD) return;
    int o = i % COUT_PAD;
    int j = i / COUT_PAD;
    wT[i] = (o < COUT) ? w[(size_t)o*CINK + j] : 0.f;
}

// ---------------- hr NCHW -> NHWC ----------------
__global__ void hr_transpose(const float* __restrict__ hr, float* __restrict__ hrT)
{
    int idx = blockIdx.x*blockDim.x + threadIdx.x;
    if (idx >= Bn*64*HW) return;
    int x = idx % Ww;
    int y = (idx / Ww) % Hh;
    int c = (idx / HW) % 64;
    int b = idx / (64*HW);
    hrT[(((size_t)b*HW) + (size_t)y*Ww + x)*64 + c] = hr[idx];
}

// ---------------- tiled direct conv / 1x1 GEMM, FFMA2 inner loop ----------------
// Block tile: OC_TILE = OCG*4 output channels  x  128 pixels (32 wide x 4 rows).
// Thread: 4 contiguous oc (as 2 packed pairs) x (4 contiguous x) x (2 rows) = 32 acc (16 u64).
// Threads = OCG*16:  tx = t&7 (x group), tyy = (t>>3)&1 (row pair), tg = t>>4 (oc group).
// Weights pre-transposed: wT[(cin*KS*KS + k)*COUT_PAD + oc]  -> LDS.128 = 2 packed oc pairs.
// Inputs staged DUPLICATED in smem so LDS.128 yields (i,i) packed operands directly.
template<int OCG, int KS, bool RELU>
__global__ void __launch_bounds__(OCG*16)
conv_tiled(const float* __restrict__ in0,
           const float* __restrict__ in1,     // second half of channel concat (or null)
           const float* __restrict__ wT,
           const float* __restrict__ bias,    // or null
           float* __restrict__ out,
           int CIN, int CIN0, int COUT, int COUT_PAD)
{
    constexpr int OC_TILE = OCG*4;
    constexpr int CK = 4;
    constexpr int KK = KS*KS;
    constexpr int SR = (KS==3) ? 6 : 4;
    constexpr int IW = (KS==3) ? 34 : 32;           // logical halo width
    constexpr int SW2 = (KS==3) ? 76 : 68;          // duplicated row stride (floats), 16B-aligned, bank-staggered
    constexpr int NT = OCG*16;

    __shared__ __align__(16) float s_in[CK][SR][SW2];   // duplicated: [..][2*x+d]
    __shared__ __align__(16) float s_w[CK][KK][OC_TILE];

    const int t   = threadIdx.x;
    const int tx  = t & 7;
    const int tyy = (t >> 3) & 1;
    const int tg  = t >> 4;

    const int noct = COUT_PAD / OC_TILE;
    const int oct  = blockIdx.z % noct;
    const int b    = blockIdx.z / noct;
    const int xb   = blockIdx.x * 32;
    const int yb   = blockIdx.y * 4;
    const int oc0  = oct * OC_TILE;
    const int x0   = tx * 4;
    const int myoc = oc0 + tg*4;

    unsigned long long bini[2];
    #pragma unroll
    for (int op = 0; op < 2; op++) {
        float blo = (bias != nullptr && (myoc+2*op  ) < COUT) ? bias[myoc+2*op  ] : 0.f;
        float bhi = (bias != nullptr && (myoc+2*op+1) < COUT) ? bias[myoc+2*op+1] : 0.f;
        bini[op] = pack2(blo, bhi);
    }

    unsigned long long acc[2][4][2];
    #pragma unroll
    for (int r = 0; r < 2; r++)
        #pragma unroll
        for (int j = 0; j < 4; j++)
            #pragma unroll
            for (int op = 0; op < 2; op++)
                acc[r][j][op] = bini[op];

    const int CIN1 = CIN - CIN0;

    for (int ci0 = 0; ci0 < CIN; ci0 += CK) {
        // stage input tile (zero-padded halo for KS==3), duplicated {v,v}
        for (int e = t; e < CK*SR*IW; e += NT) {
            int ci  = e / (SR*IW);
            int rem = e - ci*(SR*IW);
            int r   = rem / IW;
            int c   = rem - r*IW;
            int gy  = yb + r - (KS==3 ? 1 : 0);
            int gx  = xb + c - (KS==3 ? 1 : 0);
            float v = 0.f;
            if (gy >= 0 && gy < Hh && gx >= 0 && gx < Ww) {
                int cin = ci0 + ci;
                const float* p = (cin < CIN0)
                    ? (in0 + ((size_t)b*CIN0 + cin)*HW)
                    : (in1 + ((size_t)b*CIN1 + (cin - CIN0))*HW);
                v = p[gy*Ww + gx];
            }
            *(float2*)&s_in[ci][r][2*c] = make_float2(v, v);
        }
        // stage weights (coalesced: oc contiguous)
        for (int e = t; e < CK*KK*OC_TILE; e += NT) {
            int oc  = e % OC_TILE;
            int rem = e / OC_TILE;
            int k   = rem % KK;
            int ci  = rem / KK;
            s_w[ci][k][oc] = wT[((size_t)(ci0+ci)*KK + k)*COUT_PAD + oc0 + oc];
        }
        __syncthreads();

        #pragma unroll
        for (int ci = 0; ci < CK; ci++) {
            if (KS == 3) {
                #pragma unroll
                for (int ky = 0; ky < 3; ky++) {
                    const float* r0p = &s_in[ci][tyy*2 + ky    ][2*x0];
                    const float* r1p = &s_in[ci][tyy*2 + 1 + ky][2*x0];
                    ulonglong2 a0 = ((const ulonglong2*)r0p)[0];
                    ulonglong2 a1 = ((const ulonglong2*)r0p)[1];
                    ulonglong2 a2 = ((const ulonglong2*)r0p)[2];
                    ulonglong2 c0 = ((const ulonglong2*)r1p)[0];
                    ulonglong2 c1 = ((const ulonglong2*)r1p)[1];
                    ulonglong2 c2 = ((const ulonglong2*)r1p)[2];
                    unsigned long long i0[6] = {a0.x, a0.y, a1.x, a1.y, a2.x, a2.y};
                    unsigned long long i1[6] = {c0.x, c0.y, c1.x, c1.y, c2.x, c2.y};
                    #pragma unroll
                    for (int kx = 0; kx < 3; kx++) {
                        ulonglong2 wv = *(const ulonglong2*)&s_w[ci][ky*3+kx][tg*4];
                        #pragma unroll
                        for (int j = 0; j < 4; j++) {
                            acc[0][j][0] = ffma2(i0[j+kx], wv.x, acc[0][j][0]);
                            acc[0][j][1] = ffma2(i0[j+kx], wv.y, acc[0][j][1]);
                            acc[1][j][0] = ffma2(i1[j+kx], wv.x, acc[1][j][0]);
                            acc[1][j][1] = ffma2(i1[j+kx], wv.y, acc[1][j][1]);
                        }
                    }
                }
            } else {
                const float* r0p = &s_in[ci][tyy*2    ][2*x0];
                const float* r1p = &s_in[ci][tyy*2 + 1][2*x0];
                ulonglong2 a0 = ((const ulonglong2*)r0p)[0];
                ulonglong2 a1 = ((const ulonglong2*)r0p)[1];
                ulonglong2 c0 = ((const ulonglong2*)r1p)[0];
                ulonglong2 c1 = ((const ulonglong2*)r1p)[1];
                unsigned long long i0[4] = {a0.x, a0.y, a1.x, a1.y};
                unsigned long long i1[4] = {c0.x, c0.y, c1.x, c1.y};
                ulonglong2 wv = *(const ulonglong2*)&s_w[ci][0][tg*4];
                #pragma unroll
                for (int j = 0; j < 4; j++) {
                    acc[0][j][0] = ffma2(i0[j], wv.x, acc[0][j][0]);
                    acc[0][j][1] = ffma2(i0[j], wv.y, acc[0][j][1]);
                    acc[1][j][0] = ffma2(i1[j], wv.x, acc[1][j][0]);
                    acc[1][j][1] = ffma2(i1[j], wv.y, acc[1][j][1]);
                }
            }
        }
        __syncthreads();
    }

    #pragma unroll
    for (int o = 0; o < 4; o++) {
        int oc = myoc + o;
        if (oc < COUT) {
            #pragma unroll
            for (int r = 0; r < 2; r++) {
                int y = yb + tyy*2 + r;
                float4 v;
                float2 p0 = unpack2(acc[r][0][o>>1]);
                float2 p1 = unpack2(acc[r][1][o>>1]);
                float2 p2 = unpack2(acc[r][2][o>>1]);
                float2 p3 = unpack2(acc[r][3][o>>1]);
                v.x = (o&1) ? p0.y : p0.x;
                v.y = (o&1) ? p1.y : p1.x;
                v.z = (o&1) ? p2.y : p2.x;
                v.w = (o&1) ? p3.y : p3.x;
                if (RELU) {
                    v.x = fmaxf(v.x, 0.f); v.y = fmaxf(v.y, 0.f);
                    v.z = fmaxf(v.z, 0.f); v.w = fmaxf(v.w, 0.f);
                }
                *(float4*)&out[((size_t)b*COUT + oc)*HW + (size_t)y*Ww + xb + x0] = v;
            }
        }
    }
}

// ---------------- bilinear sampling (hr in NHWC; 16 channels/thread via LDG.128) ----------------
__global__ void deform_sample(const float* __restrict__ hrT,
                              const float* __restrict__ off,
                              float* __restrict__ samp)
{
    int idx = blockIdx.x*blockDim.x + threadIdx.x;
    if (idx >= Bn*9*4*HW) return;
    int x  = idx % Ww;
    int y  = (idx / Ww) % Hh;
    int cg = (idx / HW) & 3;
    int k  = (idx / (HW*4)) % 9;
    int b  = idx / (HW*36);
    int ky = k/3 - 1;
    int kx = k%3 - 1;

    size_t opix = ((size_t)b*18)*HW + (size_t)y*Ww + x;
    float dy = off[opix + (size_t)(2*k  )*HW];
    float dx = off[opix + (size_t)(2*k+1)*HW];

    float py = (float)(y + ky) + dy;
    float px = (float)(x + kx) + dx;
    float y0f = floorf(py), x0f = floorf(px);
    float wy = py - y0f, wx = px - x0f;
    int yi = (int)y0f, xi = (int)x0f;

    bool vy0 = (yi   >= 0) && (yi   <= Hh-1);
    bool vy1 = (yi+1 >= 0) && (yi+1 <= Hh-1);
    bool vx0 = (xi   >= 0) && (xi   <= Ww-1);
    bool vx1 = (xi+1 >= 0) && (xi+1 <= Ww-1);
    int yc0 = min(max(yi,   0), Hh-1);
    int yc1 = min(max(yi+1, 0), Hh-1);
    int xc0 = min(max(xi,   0), Ww-1);
    int xc1 = min(max(xi+1, 0), Ww-1);

    float w00 = (1.f-wy)*(1.f-wx) * ((vy0 && vx0) ? 1.f : 0.f);
    float w01 = (1.f-wy)*wx       * ((vy0 && vx1) ? 1.f : 0.f);
    float w10 = wy*(1.f-wx)       * ((vy1 && vx0) ? 1.f : 0.f);
    float w11 = wy*wx             * ((vy1 && vx1) ? 1.f : 0.f);

    const float* base = hrT + (size_t)b*HW*64 + cg*16;
    const float4* p00 = (const float4*)(base + ((size_t)yc0*Ww + xc0)*64);
    const float4* p01 = (const float4*)(base + ((size_t)yc0*Ww + xc1)*64);
    const float4* p10 = (const float4*)(base + ((size_t)yc1*Ww + xc0)*64);
    const float4* p11 = (const float4*)(base + ((size_t)yc1*Ww + xc1)*64);

    float o16[16];
    #pragma unroll
    for (int q = 0; q < 4; q++) {
        float4 a = p00[q], bq = p01[q], c4 = p10[q], d = p11[q];
        o16[q*4+0] = w00*a.x + w01*bq.x + w10*c4.x + w11*d.x;
        o16[q*4+1] = w00*a.y + w01*bq.y + w10*c4.y + w11*d.y;
        o16[q*4+2] = w00*a.z + w01*bq.z + w10*c4.z + w11*d.z;
        o16[q*4+3] = w00*a.w + w01*bq.w + w10*c4.w + w11*d.w;
    }

    size_t sb = ((size_t)b*576 + k)*HW + (size_t)y*Ww + x;
    #pragma unroll
    for (int c = 0; c < 16; c++)
        samp[sb + (size_t)(cg*16 + c)*9*HW] = o16[c];
}

// ---------------- launch ----------------
extern "C" void kernel_launch(void* const* d_in, const int* in_sizes, int n_in,
                              void* d_out, int out_size)
{
    (void)in_sizes; (void)n_in; (void)out_size;
    const float* lr = (const float*)d_in[0];
    const float* hr = (const float*)d_in[1];
    const float* w1 = (const float*)d_in[2];
    const float* b1 = (const float*)d_in[3];
    const float* w2 = (const float*)d_in[4];
    const float* b2 = (const float*)d_in[5];
    const float* wo = (const float*)d_in[6];
    const float* wd = (const float*)d_in[7];
    float* out = (float*)d_out;

    float *ph1, *ph2, *poff, *phrT, *psamp, *pw1T, *pw2T, *pwoT, *pwdT;
    cudaGetSymbolAddress((void**)&ph1,  g_h1);
    cudaGetSymbolAddress((void**)&ph2,  g_h2);
    cudaGetSymbolAddress((void**)&poff, g_off);
    cudaGetSymbolAddress((void**)&phrT, g_hrT);
    cudaGetSymbolAddress((void**)&psamp,g_samp);
    cudaGetSymbolAddress((void**)&pw1T, g_w1T);
    cudaGetSymbolAddress((void**)&pw2T, g_w2T);
    cudaGetSymbolAddress((void**)&pwoT, g_woT);
    cudaGetSymbolAddress((void**)&pwdT, g_wdT);

    // weight reformats + hr NHWC (cheap)
    transpose_w<<<(1152*128 + 255)/256, 256>>>(w1, pw1T, 128, 128, 1152);
    transpose_w<<<(1152*128 + 255)/256, 256>>>(w2, pw2T, 128, 128, 1152);
    transpose_w<<<(1152*32  + 255)/256, 256>>>(wo, pwoT, 18,  32,  1152);
    transpose_w<<<(576*64   + 255)/256, 256>>>(wd, pwdT, 64,  64,  576);
    hr_transpose<<<(Bn*64*HW + 255)/256, 256>>>(hr, phrT);

    // conv1: concat(lr,hr) -> 128, relu
    conv_tiled<16,3,true ><<<dim3(5,40,8), 256>>>(lr,  hr,      pw1T, b1,      ph1, 128, 64,  128, 128);
    // conv2: 128 -> 128, relu
    conv_tiled<16,3,true ><<<dim3(5,40,8), 256>>>(ph1, nullptr, pw2T, b2,      ph2, 128, 128, 128, 128);
    // offset conv: 128 -> 18 (padded 32)
    conv_tiled<8, 3,false><<<dim3(5,40,4), 128>>>(ph2, nullptr, pwoT, nullptr, poff,128, 128, 18,  32);
    // bilinear sampling
    deform_sample<<<(Bn*9*4*HW + 255)/256, 256>>>(phrT, poff, psamp);
    // deform contraction as 1x1 conv: 576 -> 64
    conv_tiled<16,1,false><<<dim3(5,40,4), 256>>>(psamp, nullptr, pwdT, nullptr, out, 576, 576, 64, 64);
}